// round 16
// baseline (speedup 1.0000x reference)
#include <cuda_runtime.h>
#include <cuda_fp16.h>
#include <cstdint>

#define BS   2
#define SEQ  4096
#define HH   32
#define LLC  64
#define CC   (SEQ/LLC)   // 64
#define RSH  40          // words per half2 table row (32 data + 8 pad)
#define GSTR (HH*64)

__device__ __half g_states[(size_t)BS*CC*HH*64*64];  // [b][c][h][p][n] fp16
__device__ __half g_ydiag [(size_t)BS*SEQ*HH*64];    // [b][s][h][p]    fp16
__device__ float  g_el    [(size_t)BS*CC*HH*64];     // per-chunk exp(cumsum)

typedef unsigned int u32;

__device__ __forceinline__ u32 f22h(float lo, float hi){
    u32 r; asm("cvt.rn.f16x2.f32 %0, %1, %2;" : "=r"(r) : "f"(hi), "f"(lo)); return r;
}
__device__ __forceinline__ float2 h22f(u32 v){
    __half2 h = *reinterpret_cast<__half2*>(&v);
    return __half22float2(h);
}
// D(16x8,f32) += A(16x16,f16 row) * B(16x8,f16 col)
__device__ __forceinline__ void mma16(float* d, const u32* a, u32 b0, u32 b1){
    asm volatile("mma.sync.aligned.m16n8k16.row.col.f32.f16.f16.f32 "
        "{%0,%1,%2,%3}, {%4,%5,%6,%7}, {%8,%9}, {%0,%1,%2,%3};"
        : "+f"(d[0]), "+f"(d[1]), "+f"(d[2]), "+f"(d[3])
        : "r"(a[0]), "r"(a[1]), "r"(a[2]), "r"(a[3]), "r"(b0), "r"(b1));
}
// skew-paired half2 layout
__device__ __forceinline__ int WH(int r, int w){
    return 2*(((4*(w>>3)) + (w&3) + (r>>2)) & 15) + ((w>>2)&1);
}
__device__ __forceinline__ void stpw(u32* t, int r, int w, u32 v){
    t[r*RSH + WH(r,w)] = v;
}
__device__ __forceinline__ uint2 ldpairH(const u32* t, int r, int kk, int qc){
    return *(const uint2*)&t[r*RSH + 2*((4*kk + qc + (r>>2)) & 15)];
}
__device__ __forceinline__ void ldfragH(const u32* t, int r, int kk, int qc, u32* a){
    uint2 lo = ldpairH(t, r, kk, qc), hi = ldpairH(t, r+8, kk, qc);
    a[0] = lo.x; a[1] = hi.x; a[2] = lo.y; a[3] = hi.y;
}

// ===========================================================================
// K1: per (b,c,h). 256 thr / 8 warps; warp tile 16 rows x 32 cols (R13 cfg).
// Y_diag (fp16) -> g_ydiag, chunk states (fp16) -> g_states, el -> g_el.
// ===========================================================================
__global__ __launch_bounds__(256, 3) void ssd_k1(
    const float* __restrict__ X, const float* __restrict__ A,
    const float* __restrict__ Bm, const float* __restrict__ Cm)
{
    extern __shared__ u32 smw[];
    u32* sXt = smw;                 // [p][s-halves]
    u32* sB  = smw + 64*RSH;        // [s][n-halves]
    u32* sC  = smw + 2*64*RSH;      // [l][n-halves] -> sG [l][s-halves]
    u32* sBt = smw + 3*64*RSH;      // [n][l-halves], dec folded
    float* aA   = (float*)(smw + 4*64*RSH);
    float* el   = aA + 64;
    float* einv = el + 64;
    float* decs = einv + 64;
    u32*   sG   = sC;

    const int h = blockIdx.x, c = blockIdx.y, b = blockIdx.z;
    const int tid = threadIdx.x, wid = tid >> 5, lane = tid & 31;
    const int qr = lane >> 2, qc = lane & 3;
    const int r0 = (wid >> 1) * 16;       // 4 rowgroups of 16
    const int cB = (wid & 1) * 32;        // 2 col halves of 32
    const int base = ((b*SEQ + c*LLC)*HH + h)*64;

    // phase A: load B, C as half2 (paired layout); aA
    #pragma unroll
    for (int i = tid; i < 1024; i += 256) {
        int row = i >> 4, c4 = (i & 15) << 2;
        int g = base + row*GSTR + c4;
        float4 bv = *(const float4*)&Bm[g];
        float4 cv = *(const float4*)&Cm[g];
        stpw(sB, row, c4>>1,     f22h(bv.x, bv.y));
        stpw(sB, row, (c4>>1)+1, f22h(bv.z, bv.w));
        stpw(sC, row, c4>>1,     f22h(cv.x, cv.y));
        stpw(sC, row, (c4>>1)+1, f22h(cv.z, cv.w));
    }
    if (tid < 64) aA[tid] = A[(b*SEQ + c*LLC + tid)*HH + h];

    // phase C: X transposed straight from global into sXt[p][s-halves]
    #pragma unroll
    for (int m = 0; m < 4; m++) {
        int w = wid*4 + m;                        // s-pair
        const float2 x0 = *(const float2*)&X[base + (2*w)*GSTR + 2*lane];
        const float2 x1 = *(const float2*)&X[base + (2*w+1)*GSTR + 2*lane];
        stpw(sXt, 2*lane,   w, f22h(x0.x, x1.x));
        stpw(sXt, 2*lane+1, w, f22h(x0.y, x1.y));
    }
    __syncthreads();

    if (tid < 64) {
        float s = 0.f, mine = 0.f;
        #pragma unroll
        for (int j = 0; j < 64; j++) { s += aA[j]; if (j == tid) mine = s; }
        el[tid]   = __expf(mine);
        einv[tid] = __expf(-mine);
        decs[tid] = __expf(s - mine);
        g_el[((b*CC + c)*HH + h)*64 + tid] = el[tid];
    }
    __syncthreads();

    // phase D: sBt[n][l-halves] = dec[l]*B[l][n]
    #pragma unroll
    for (int m = 0; m < 4; m++) {
        int w = wid*4 + m;                        // l-pair
        float d0 = decs[2*w], d1 = decs[2*w+1];
        u32 v0 = sB[(2*w)*RSH   + WH(2*w,   lane)];
        u32 v1 = sB[(2*w+1)*RSH + WH(2*w+1, lane)];
        float2 fa = h22f(v0), fb = h22f(v1);
        stpw(sBt, 2*lane,   w, f22h(fa.x*d0, fb.x*d1));
        stpw(sBt, 2*lane+1, w, f22h(fa.y*d0, fb.y*d1));
    }

    // ---- mm1: G[l,s] = sum_n C[l,n]*B[s,n] ----
    float g[4][4] = {};
    #pragma unroll
    for (int kk = 0; kk < 4; kk++) {
        u32 a0[4];
        ldfragH(sC, r0+qr, kk, qc, a0);
        #pragma unroll
        for (int t = 0; t < 4; t++) {
            uint2 bb = ldpairH(sB, cB + t*8 + qr, kk, qc);
            mma16(g[t], a0, bb.x, bb.y);
        }
    }
    __syncthreads();   // mm1 reads of sC/sB done (covers phase D too)

    // mask + decay into sG[l][s-halves]
    {
        int l0v = r0 + qr, l1v = l0v + 8;
        float e0 = el[l0v], e1 = el[l1v];
        #pragma unroll
        for (int t = 0; t < 4; t++) {
            int s0 = cB + t*8 + 2*qc, s1 = s0 + 1;
            int w  = ((cB + t*8) >> 1) + qc;
            float i0 = einv[s0], i1 = einv[s1];
            float v0 = (s0 <= l0v) ? g[t][0]*e0*i0 : 0.f;
            float v1 = (s1 <= l0v) ? g[t][1]*e0*i1 : 0.f;
            float v2 = (s0 <= l1v) ? g[t][2]*e1*i0 : 0.f;
            float v3 = (s1 <= l1v) ? g[t][3]*e1*i1 : 0.f;
            stpw(sG, l0v, w, f22h(v0, v1));
            stpw(sG, l1v, w, f22h(v2, v3));
        }
    }
    __syncthreads();

    // ---- mm2: Y[l,p] = sum_s G[l,s]*X[s,p]; store immediately ----
    {
        float y[4][4] = {};
        #pragma unroll
        for (int kk = 0; kk < 4; kk++) {
            u32 a0[4];
            ldfragH(sG, r0+qr, kk, qc, a0);
            #pragma unroll
            for (int t = 0; t < 4; t++) {
                uint2 bb = ldpairH(sXt, cB + t*8 + qr, kk, qc);
                mma16(y[t], a0, bb.x, bb.y);
            }
        }
        int row0 = r0 + qr, row1 = r0 + qr + 8;
        #pragma unroll
        for (int t = 0; t < 4; t++) {
            int c0 = cB + t*8 + 2*qc;
            *(u32*)&g_ydiag[base + row0*GSTR + c0] = f22h(y[t][0], y[t][1]);
            *(u32*)&g_ydiag[base + row1*GSTR + c0] = f22h(y[t][2], y[t][3]);
        }
    }

    // ---- mm3: S[p,n] = sum_l Xt[p,l]*(dec[l]*B[l,n]); store immediately ----
    {
        float st[4][4] = {};
        #pragma unroll
        for (int kk = 0; kk < 4; kk++) {
            u32 a0[4];
            ldfragH(sXt, r0+qr, kk, qc, a0);
            #pragma unroll
            for (int t = 0; t < 4; t++) {
                uint2 bb = ldpairH(sBt, cB + t*8 + qr, kk, qc);
                mma16(st[t], a0, bb.x, bb.y);
            }
        }
        const int sbase = ((b*CC + c)*HH + h)*4096;
        int row0 = r0 + qr, row1 = r0 + qr + 8;
        #pragma unroll
        for (int t = 0; t < 4; t++) {
            int c0 = cB + t*8 + 2*qc;
            *(u32*)&g_states[sbase + row0*64 + c0] = f22h(st[t][0], st[t][1]);
            *(u32*)&g_states[sbase + row1*64 + c0] = f22h(st[t][2], st[t][3]);
        }
    }
}

// ===========================================================================
// K23 fused: 128 persistent blocks = (b, h, p-half). Running prefix state in
// fp32 registers (8/thread); per chunk: mma Y_off = C*St^T + ydiag -> Y,
// then state = state*ea + chunk_states. All inputs prefetched 1 chunk ahead.
// ===========================================================================
__global__ __launch_bounds__(256) void ssd_k23(
    const float* __restrict__ Cm, float* __restrict__ Y)
{
    extern __shared__ u32 smw[];
    u32* sC  = smw;                  // [l 64][n-halves] skew
    u32* sS  = smw + 64*RSH;         // [p-local 32][n-halves] skew
    float* sEl = (float*)(smw + 96*RSH);   // 64

    const int blk = blockIdx.x;              // b*64 + h*2 + ph
    const int ph = blk & 1, h = (blk >> 1) & 31, b = blk >> 6;
    const int tid = threadIdx.x, wid = tid >> 5, lane = tid & 31;
    const int qr = lane >> 2, qc = lane & 3;
    const int rg = (wid >> 1) * 16;          // l rowgroup (4 of 16)
    const int pw = (wid & 1) * 16;           // p sub-half within the 32

    const int pl  = tid >> 3;                // local p row 0..31
    const int n0w = (tid & 7) * 4;           // first of 4 n-pair words

    float rs[8] = {0,0,0,0,0,0,0,0};         // running prefix state (fp32)

    u32 pc[8];      // prefetched C chunk (16 f32 -> 8 fp16 words)
    u32 pst[4];     // prefetched chunk-states slice
    u32 pyd[4];     // prefetched ydiag fragments
    float pel = 0.f;

    // ---- prologue: prefetch chunk 0 ----
    {
        const int c = 0;
        const int cb = ((b*SEQ + c*LLC)*HH + h)*64;
        #pragma unroll
        for (int m = 0; m < 4; m++) {
            int i = tid + 256*m, row = i >> 4, c4 = (i & 15) << 2;
            float4 cv = *(const float4*)&Cm[cb + row*GSTR + c4];
            pc[2*m]   = f22h(cv.x, cv.y);
            pc[2*m+1] = f22h(cv.z, cv.w);
        }
        const u32* sp = (const u32*)g_states;
        size_t so = ((size_t)(b*CC + c)*HH + h)*2048 + ph*1024 + tid*4;
        #pragma unroll
        for (int m = 0; m < 4; m++) pst[m] = sp[so + m];
        int row0 = rg + qr, row1 = row0 + 8;
        #pragma unroll
        for (int t = 0; t < 2; t++) {
            int c0 = ph*32 + pw + t*8 + 2*qc;
            pyd[t]   = *(const u32*)&g_ydiag[cb + row0*GSTR + c0];
            pyd[2+t] = *(const u32*)&g_ydiag[cb + row1*GSTR + c0];
        }
        if (tid < 64) pel = g_el[((b*CC + c)*HH + h)*64 + tid];
    }

    for (int c = 0; c < CC; c++) {
        const int cb = ((b*SEQ + c*LLC)*HH + h)*64;
        const int cn = (c+1 < CC) ? c+1 : c;          // clamped prefetch chunk
        const int cbn = ((b*SEQ + cn*LLC)*HH + h)*64;

        __syncthreads();   // protect prior iteration's smem reads

        // stage chunk c into smem
        #pragma unroll
        for (int m = 0; m < 4; m++) {
            int i = tid + 256*m, row = i >> 4, c4 = (i & 15) << 2;
            stpw(sC, row, c4>>1,     pc[2*m]);
            stpw(sC, row, (c4>>1)+1, pc[2*m+1]);
        }
        #pragma unroll
        for (int m = 0; m < 4; m++)
            stpw(sS, pl, n0w + m, f22h(rs[2*m], rs[2*m+1]));
        if (tid < 64) sEl[tid] = pel;
        __syncthreads();

        // update running state with chunk c's states (snapshot already in sS)
        {
            float ea = sEl[63];
            #pragma unroll
            for (int m = 0; m < 4; m++) {
                float2 f = h22f(pst[m]);
                rs[2*m]   = rs[2*m]*ea   + f.x;
                rs[2*m+1] = rs[2*m+1]*ea + f.y;
            }
        }

        // prefetch C + states for chunk c+1 (hidden behind mma/epilogue)
        #pragma unroll
        for (int m = 0; m < 4; m++) {
            int i = tid + 256*m, row = i >> 4, c4 = (i & 15) << 2;
            float4 cv = *(const float4*)&Cm[cbn + row*GSTR + c4];
            pc[2*m]   = f22h(cv.x, cv.y);
            pc[2*m+1] = f22h(cv.z, cv.w);
        }
        {
            const u32* sp = (const u32*)g_states;
            size_t so = ((size_t)(b*CC + cn)*HH + h)*2048 + ph*1024 + tid*4;
            #pragma unroll
            for (int m = 0; m < 4; m++) pst[m] = sp[so + m];
        }

        // mma: y[l, p] = sum_n C[l,n] * St[p,n]
        float y[2][4] = {};
        #pragma unroll
        for (int kk = 0; kk < 4; kk++) {
            u32 a0[4];
            ldfragH(sC, rg+qr, kk, qc, a0);
            #pragma unroll
            for (int t = 0; t < 2; t++) {
                uint2 bb = ldpairH(sS, pw + t*8 + qr, kk, qc);
                mma16(y[t], a0, bb.x, bb.y);
            }
        }

        // epilogue: Y = ydiag + el * acc
        {
            int row0 = rg + qr, row1 = row0 + 8;
            float e0 = sEl[row0], e1 = sEl[row1];
            #pragma unroll
            for (int t = 0; t < 2; t++) {
                int c0 = ph*32 + pw + t*8 + 2*qc;
                float2 d0 = h22f(pyd[t]);
                float2 d1 = h22f(pyd[2+t]);
                *(float2*)&Y[cb + row0*GSTR + c0] =
                    make_float2(d0.x + e0*y[t][0], d0.y + e0*y[t][1]);
                *(float2*)&Y[cb + row1*GSTR + c0] =
                    make_float2(d1.x + e1*y[t][2], d1.y + e1*y[t][3]);
            }
            // prefetch ydiag + el for chunk c+1
            #pragma unroll
            for (int t = 0; t < 2; t++) {
                int c0 = ph*32 + pw + t*8 + 2*qc;
                pyd[t]   = *(const u32*)&g_ydiag[cbn + row0*GSTR + c0];
                pyd[2+t] = *(const u32*)&g_ydiag[cbn + row1*GSTR + c0];
            }
            if (tid < 64) pel = g_el[((b*CC + cn)*HH + h)*64 + tid];
        }
    }
}

// ---------------------------------------------------------------------------
extern "C" void kernel_launch(void* const* d_in, const int* in_sizes, int n_in,
                              void* d_out, int out_size)
{
    const float* X  = (const float*)d_in[0];
    const float* A  = (const float*)d_in[1];
    const float* Bm = (const float*)d_in[2];
    const float* Cm = (const float*)d_in[3];
    float* Y = (float*)d_out;

    const int sm1  = (4*64*RSH + 4*64) * 4;   // 41984 B
    const int sm23 = (96*RSH + 64) * 4;       // 15616 B
    cudaFuncSetAttribute(ssd_k1,  cudaFuncAttributeMaxDynamicSharedMemorySize, sm1);
    cudaFuncSetAttribute(ssd_k23, cudaFuncAttributeMaxDynamicSharedMemorySize, sm23);

    dim3 grid(HH, CC, BS);
    ssd_k1<<<grid, 256, sm1>>>(X, A, Bm, Cm);
    ssd_k23<<<BS*HH*2, 256, sm23>>>(Cm, Y);
}